// round 1
// baseline (speedup 1.0000x reference)
#include <cuda_runtime.h>
#include <math.h>

#define BATCH 4
#define SEQ   2048
#define DMODEL 1024
#define NH    8
#define HD    128
#define HDIM  1024

// Scratch (device globals: allocation-free rule)
__device__ float g_qkv[(size_t)BATCH * SEQ * 3 * HDIM];   // [B,T,3*HDIM]
__device__ float g_q[(size_t)BATCH * NH * SEQ * HD];      // [B,H,T,D]
__device__ float g_k[(size_t)BATCH * NH * SEQ * HD];
__device__ float g_v[(size_t)BATCH * NH * SEQ * HD];
__device__ float g_y[(size_t)BATCH * SEQ * HDIM];         // [B,T,HDIM]

// ---------------------------------------------------------------------------
// C[M,N] = A[M,K] * B[N,K]^T   (both row-major, K contiguous)
// 128x128 tile, BK=8, 256 threads, 8x8 per thread in 2x 4-wide quadrants.
// ---------------------------------------------------------------------------
__global__ __launch_bounds__(256, 2) void sgemm_nt(
    const float* __restrict__ A, const float* __restrict__ Bm,
    float* __restrict__ C, int M, int N, int K)
{
    __shared__ float As[8][128];
    __shared__ float Bs[8][128];
    const int tid = threadIdx.x;
    const int tx = tid & 15, ty = tid >> 4;

    const float* Ab = A + (size_t)blockIdx.y * 128 * K;
    const float* Bb = Bm + (size_t)blockIdx.x * 128 * K;

    float acc[8][8];
#pragma unroll
    for (int i = 0; i < 8; i++)
#pragma unroll
        for (int j = 0; j < 8; j++) acc[i][j] = 0.f;

    const int lr = tid >> 1;        // 0..127 tile row
    const int lk = (tid & 1) * 4;   // 0 or 4 within BK
    const float* Ap = Ab + (size_t)lr * K + lk;
    const float* Bp = Bb + (size_t)lr * K + lk;

    for (int k0 = 0; k0 < K; k0 += 8) {
        float4 av = *(const float4*)(Ap + k0);
        float4 bv = *(const float4*)(Bp + k0);
        __syncthreads();
        As[lk + 0][lr] = av.x; As[lk + 1][lr] = av.y;
        As[lk + 2][lr] = av.z; As[lk + 3][lr] = av.w;
        Bs[lk + 0][lr] = bv.x; Bs[lk + 1][lr] = bv.y;
        Bs[lk + 2][lr] = bv.z; Bs[lk + 3][lr] = bv.w;
        __syncthreads();
#pragma unroll
        for (int kk = 0; kk < 8; kk++) {
            float4 a0 = *(const float4*)&As[kk][ty * 4];
            float4 a1 = *(const float4*)&As[kk][64 + ty * 4];
            float4 b0 = *(const float4*)&Bs[kk][tx * 4];
            float4 b1 = *(const float4*)&Bs[kk][64 + tx * 4];
            float a[8] = {a0.x, a0.y, a0.z, a0.w, a1.x, a1.y, a1.z, a1.w};
            float b[8] = {b0.x, b0.y, b0.z, b0.w, b1.x, b1.y, b1.z, b1.w};
#pragma unroll
            for (int i = 0; i < 8; i++)
#pragma unroll
                for (int j = 0; j < 8; j++)
                    acc[i][j] = fmaf(a[i], b[j], acc[i][j]);
        }
    }

#pragma unroll
    for (int i = 0; i < 8; i++) {
        int row = blockIdx.y * 128 + (i < 4 ? ty * 4 + i : 64 + ty * 4 + (i - 4));
        float* Cp = C + (size_t)row * N + blockIdx.x * 128;
        *(float4*)(Cp + tx * 4) =
            make_float4(acc[i][0], acc[i][1], acc[i][2], acc[i][3]);
        *(float4*)(Cp + 64 + tx * 4) =
            make_float4(acc[i][4], acc[i][5], acc[i][6], acc[i][7]);
    }
}

// ---------------------------------------------------------------------------
// Per (b,t,h): RMS-norm q,k over D=128; RoPE; v = l0*v + l1*ve.
// Writes Q,K,V in [B,H,T,D] layout for the attention kernel.
// ---------------------------------------------------------------------------
__global__ __launch_bounds__(128) void prep_kernel(
    const float* __restrict__ qkv, const float* __restrict__ ve,
    const float* __restrict__ lam,
    float* __restrict__ Q, float* __restrict__ K, float* __restrict__ V)
{
    const int idx = blockIdx.x;          // (b*T + t)*H + h
    const int h = idx % NH;
    const int bt = idx / NH;
    const int t = bt % SEQ;
    const int b = bt / SEQ;
    const int d = threadIdx.x;           // 0..127

    const float* base = qkv + (size_t)bt * 3 * HDIM;
    float qv = base[h * HD + d];
    float kv = base[HDIM + h * HD + d];
    float vv = base[2 * HDIM + h * HD + d];

    float sq = qv * qv, sk = kv * kv;
#pragma unroll
    for (int o = 16; o; o >>= 1) {
        sq += __shfl_xor_sync(0xffffffffu, sq, o);
        sk += __shfl_xor_sync(0xffffffffu, sk, o);
    }
    __shared__ float wq[4], wk[4];
    if ((d & 31) == 0) { wq[d >> 5] = sq; wk[d >> 5] = sk; }
    __syncthreads();
    float tq = (wq[0] + wq[1]) + (wq[2] + wq[3]);
    float tk = (wk[0] + wk[1]) + (wk[2] + wk[3]);
    const float EPS = 1.1920929e-7f;  // finfo(float32).eps
    float rq = rsqrtf(tq * (1.0f / 128.0f) + EPS);
    float rk = rsqrtf(tk * (1.0f / 128.0f) + EPS);

    __shared__ float nq[128], nk[128];
    nq[d] = qv * rq;
    nk[d] = kv * rk;
    __syncthreads();

    // RoPE tables: freq[i] = (1/1024)^(i/31) for i<32, else 0 (D/4 = 32)
    const int i = d & 63;
    float c, s;
    if (i < 32) {
        float xi = (float)i / 31.0f;
        float f = (float)exp2(-10.0 * (double)xi);   // accurate table value
        float th = (float)t * f;
        c = cosf(th);
        s = sinf(th);
    } else {
        c = 1.0f; s = 0.0f;
    }
    float qo, ko;
    if (d < 64) { qo = nq[d] * c + nq[d + 64] * s; ko = nk[d] * c + nk[d + 64] * s; }
    else        { qo = nq[d] * c - nq[d - 64] * s; ko = nk[d] * c - nk[d - 64] * s; }

    float vo = lam[0] * vv + lam[1] * ve[(size_t)bt * HDIM + h * HD + d];

    size_t o = ((size_t)(b * NH + h) * SEQ + t) * HD + d;
    Q[o] = qo; K[o] = ko; V[o] = vo;
}

// ---------------------------------------------------------------------------
// Flash attention, fp32. One CTA per (b,h, 64-row Q tile). BM=BN=64.
// Q,K stored kd-major in smem so S-loop is 2x LDS.128 per k vs 16 FMA.
// ---------------------------------------------------------------------------
#define FLASH_SMEM_FLOATS (128*64 + 128*64 + 64*132 + 64*65)

__global__ __launch_bounds__(256) void flash_kernel(
    const float* __restrict__ Qg, const float* __restrict__ Kg,
    const float* __restrict__ Vg, float* __restrict__ Y)
{
    extern __shared__ float sm[];
    float* Qs = sm;                 // [kd=128][r=64]
    float* Ks = Qs + 128 * 64;      // [kd=128][c=64]
    float* Vs = Ks + 128 * 64;      // [c=64][d=128] stride 132
    float* Ps = Vs + 64 * 132;      // [r=64][c=64]  stride 65

    const int qt = blockIdx.x;
    const int bh = blockIdx.y;
    const int tid = threadIdx.x;
    const int tx = tid & 15, ty = tid >> 4;

    const float* Qh = Qg + (size_t)bh * SEQ * HD;
    const float* Kh = Kg + (size_t)bh * SEQ * HD;
    const float* Vh = Vg + (size_t)bh * SEQ * HD;

    const int lrow = tid >> 2;          // 0..63
    const int lcol = (tid & 3) * 32;    // d-chunk
    {
        const float* src = Qh + (size_t)(qt * 64 + lrow) * HD + lcol;
        const float scale = 0.088388347648318447f;  // 1/sqrt(128)
#pragma unroll
        for (int u = 0; u < 8; u++) {
            float4 v = *(const float4*)(src + u * 4);
            int kd = lcol + u * 4;
            Qs[(kd + 0) * 64 + lrow] = v.x * scale;
            Qs[(kd + 1) * 64 + lrow] = v.y * scale;
            Qs[(kd + 2) * 64 + lrow] = v.z * scale;
            Qs[(kd + 3) * 64 + lrow] = v.w * scale;
        }
    }

    float m_i[4], l_i[4], acc[4][8];
#pragma unroll
    for (int i = 0; i < 4; i++) {
        m_i[i] = -1e30f; l_i[i] = 0.f;
#pragma unroll
        for (int j = 0; j < 8; j++) acc[i][j] = 0.f;
    }

    for (int kt = 0; kt <= qt; kt++) {
        __syncthreads();
        {
            const float* ks = Kh + (size_t)(kt * 64 + lrow) * HD + lcol;
            const float* vs = Vh + (size_t)(kt * 64 + lrow) * HD + lcol;
#pragma unroll
            for (int u = 0; u < 8; u++) {
                float4 v = *(const float4*)(ks + u * 4);
                int kd = lcol + u * 4;
                Ks[(kd + 0) * 64 + lrow] = v.x;
                Ks[(kd + 1) * 64 + lrow] = v.y;
                Ks[(kd + 2) * 64 + lrow] = v.z;
                Ks[(kd + 3) * 64 + lrow] = v.w;
                float4 w = *(const float4*)(vs + u * 4);
                *(float4*)&Vs[lrow * 132 + lcol + u * 4] = w;
            }
        }
        __syncthreads();

        float s[4][4];
#pragma unroll
        for (int i = 0; i < 4; i++)
#pragma unroll
            for (int j = 0; j < 4; j++) s[i][j] = 0.f;

#pragma unroll 4
        for (int kd = 0; kd < 128; kd++) {
            float4 a = *(const float4*)&Qs[kd * 64 + ty * 4];
            float4 b = *(const float4*)&Ks[kd * 64 + tx * 4];
            float aa[4] = {a.x, a.y, a.z, a.w};
            float bb[4] = {b.x, b.y, b.z, b.w};
#pragma unroll
            for (int i = 0; i < 4; i++)
#pragma unroll
                for (int j = 0; j < 4; j++)
                    s[i][j] = fmaf(aa[i], bb[j], s[i][j]);
        }

        if (kt == qt) {   // causal mask on diagonal tile
#pragma unroll
            for (int i = 0; i < 4; i++)
#pragma unroll
                for (int j = 0; j < 4; j++)
                    if (tx * 4 + j > ty * 4 + i) s[i][j] = -1e30f;
        }

#pragma unroll
        for (int i = 0; i < 4; i++) {
            float mt = fmaxf(fmaxf(s[i][0], s[i][1]), fmaxf(s[i][2], s[i][3]));
#pragma unroll
            for (int o = 8; o; o >>= 1)
                mt = fmaxf(mt, __shfl_xor_sync(0xffffffffu, mt, o));
            float mn = fmaxf(m_i[i], mt);
            float corr = __expf(m_i[i] - mn);
            m_i[i] = mn;
            float rs = 0.f;
#pragma unroll
            for (int j = 0; j < 4; j++) {
                s[i][j] = __expf(s[i][j] - mn);
                rs += s[i][j];
            }
#pragma unroll
            for (int o = 8; o; o >>= 1)
                rs += __shfl_xor_sync(0xffffffffu, rs, o);
            l_i[i] = l_i[i] * corr + rs;
#pragma unroll
            for (int j = 0; j < 8; j++) acc[i][j] *= corr;
        }

#pragma unroll
        for (int i = 0; i < 4; i++)
#pragma unroll
            for (int j = 0; j < 4; j++)
                Ps[(ty * 4 + i) * 65 + tx * 4 + j] = s[i][j];
        __syncthreads();

#pragma unroll 2
        for (int c = 0; c < 64; c++) {
            float4 v0 = *(const float4*)&Vs[c * 132 + tx * 4];
            float4 v1 = *(const float4*)&Vs[c * 132 + 64 + tx * 4];
#pragma unroll
            for (int i = 0; i < 4; i++) {
                float p = Ps[(ty * 4 + i) * 65 + c];
                acc[i][0] = fmaf(p, v0.x, acc[i][0]);
                acc[i][1] = fmaf(p, v0.y, acc[i][1]);
                acc[i][2] = fmaf(p, v0.z, acc[i][2]);
                acc[i][3] = fmaf(p, v0.w, acc[i][3]);
                acc[i][4] = fmaf(p, v1.x, acc[i][4]);
                acc[i][5] = fmaf(p, v1.y, acc[i][5]);
                acc[i][6] = fmaf(p, v1.z, acc[i][6]);
                acc[i][7] = fmaf(p, v1.w, acc[i][7]);
            }
        }
    }

    const int b = bh / NH, h = bh % NH;
#pragma unroll
    for (int i = 0; i < 4; i++) {
        float inv = 1.f / l_i[i];
        int t = qt * 64 + ty * 4 + i;
        float* yr = Y + ((size_t)(b * SEQ + t)) * HDIM + h * HD;
        *(float4*)(yr + tx * 4) =
            make_float4(acc[i][0] * inv, acc[i][1] * inv, acc[i][2] * inv, acc[i][3] * inv);
        *(float4*)(yr + 64 + tx * 4) =
            make_float4(acc[i][4] * inv, acc[i][5] * inv, acc[i][6] * inv, acc[i][7] * inv);
    }
}

// ---------------------------------------------------------------------------
extern "C" void kernel_launch(void* const* d_in, const int* in_sizes, int n_in,
                              void* d_out, int out_size)
{
    const float* x        = (const float*)d_in[0];
    const float* ve       = (const float*)d_in[1];
    const float* qkv_w    = (const float*)d_in[2];   // [3*HDIM, DIM]
    const float* lambdas  = (const float*)d_in[3];
    const float* c_proj_w = (const float*)d_in[4];   // [DIM, HDIM]
    float* out = (float*)d_out;

    float *qkv, *Q, *K, *V, *Y;
    cudaGetSymbolAddress((void**)&qkv, g_qkv);
    cudaGetSymbolAddress((void**)&Q, g_q);
    cudaGetSymbolAddress((void**)&K, g_k);
    cudaGetSymbolAddress((void**)&V, g_v);
    cudaGetSymbolAddress((void**)&Y, g_y);

    // 1) qkv = x @ qkv_w^T : [8192,1024] x [3072,1024]^T
    sgemm_nt<<<dim3(3 * HDIM / 128, BATCH * SEQ / 128), 256>>>(
        x, qkv_w, qkv, BATCH * SEQ, 3 * HDIM, DMODEL);

    // 2) rms-norm + rope + v-mix, relayout to [B,H,T,D]
    prep_kernel<<<BATCH * SEQ * NH, 128>>>(qkv, ve, lambdas, Q, K, V);

    // 3) causal flash attention -> Y [B,T,HDIM]
    cudaFuncSetAttribute(flash_kernel,
                         cudaFuncAttributeMaxDynamicSharedMemorySize,
                         FLASH_SMEM_FLOATS * 4);
    flash_kernel<<<dim3(SEQ / 64, BATCH * NH), 256, FLASH_SMEM_FLOATS * 4>>>(
        Q, K, V, Y);

    // 4) out = Y @ c_proj_w^T : [8192,1024] x [1024,1024]^T
    sgemm_nt<<<dim3(DMODEL / 128, BATCH * SEQ / 128), 256>>>(
        Y, c_proj_w, out, BATCH * SEQ, DMODEL, HDIM);
}

// round 3
// speedup vs baseline: 2.4139x; 2.4139x over previous
#include <cuda_runtime.h>
#include <cuda_bf16.h>
#include <cstdint>
#include <math.h>

#define BATCH 4
#define SEQ   2048
#define DMODEL 1024
#define NH    8
#define HD    128
#define HDIM  1024

// ---------------------------------------------------------------------------
// Scratch (device globals: allocation-free rule)
// ---------------------------------------------------------------------------
__device__ float g_qkv[(size_t)BATCH * SEQ * 3 * HDIM];          // [B,T,3*HDIM]
__device__ float g_v[(size_t)BATCH * NH * SEQ * HD];             // [B,H,T,D] fp32
__device__ float g_y[(size_t)BATCH * SEQ * HDIM];                // [B,T,HDIM]
__device__ __nv_bfloat16 g_qh[(size_t)BATCH * NH * SEQ * HD];    // [B,H,T,D]
__device__ __nv_bfloat16 g_ql[(size_t)BATCH * NH * SEQ * HD];
__device__ __nv_bfloat16 g_kh[(size_t)BATCH * NH * SEQ * HD];
__device__ __nv_bfloat16 g_kl[(size_t)BATCH * NH * SEQ * HD];
__device__ __nv_bfloat16 g_vh[(size_t)BATCH * NH * HD * SEQ];    // [B,H,D,T]
__device__ __nv_bfloat16 g_vl[(size_t)BATCH * NH * HD * SEQ];

// ---------------------------------------------------------------------------
// PTX helpers (all standard sm_80-class: valid at compute_103 target)
// ---------------------------------------------------------------------------
__device__ __forceinline__ uint32_t smem_u32(const void* p) {
    uint32_t a;
    asm("{ .reg .u64 t; cvta.to.shared.u64 t, %1; cvt.u32.u64 %0, t; }"
        : "=r"(a) : "l"(p));
    return a;
}

#define LDMX4(r, addr) \
    asm volatile("ldmatrix.sync.aligned.m8n8.x4.shared.b16 {%0,%1,%2,%3}, [%4];" \
        : "=r"((r)[0]), "=r"((r)[1]), "=r"((r)[2]), "=r"((r)[3]) : "r"(addr))

#define MMA_BF16(d, a, b0, b1) \
    asm volatile("mma.sync.aligned.m16n8k16.row.col.f32.bf16.bf16.f32 " \
        "{%0,%1,%2,%3},{%4,%5,%6,%7},{%8,%9},{%0,%1,%2,%3};" \
        : "+f"((d)[0]), "+f"((d)[1]), "+f"((d)[2]), "+f"((d)[3]) \
        : "r"((a)[0]), "r"((a)[1]), "r"((a)[2]), "r"((a)[3]), "r"(b0), "r"(b1))

#define STSV2(addr, w0, w1) \
    asm volatile("st.shared.v2.b32 [%0], {%1,%2};" :: "r"(addr), "r"(w0), "r"(w1) : "memory")

#define CP_ASYNC16(dst, src) \
    asm volatile("cp.async.cg.shared.global [%0], [%1], 16;" :: "r"(dst), "l"(src) : "memory")
#define CP_COMMIT() asm volatile("cp.async.commit_group;" ::: "memory")
#define CP_WAIT0()  asm volatile("cp.async.wait_group 0;" ::: "memory")
#define CP_WAIT1()  asm volatile("cp.async.wait_group 1;" ::: "memory")

// pack two fp32 -> bf16x2 (e0 in low half, e1 in high half)
__device__ __forceinline__ uint32_t packbf(float e0, float e1) {
    uint32_t d;
    asm("cvt.rn.bf16x2.f32 %0, %1, %2;" : "=r"(d) : "f"(e1), "f"(e0));
    return d;
}
__device__ __forceinline__ float bfx2_lo(uint32_t p) { return __uint_as_float(p << 16); }
__device__ __forceinline__ float bfx2_hi(uint32_t p) { return __uint_as_float(p & 0xFFFF0000u); }

// ===========================================================================
// GEMM: C[M,N] = A[M,K] * B[N,K]^T, fp32 in/out, bf16-split 3-term mma.sync.
// CTA 128x128, 256 thr (8 warps as 2x4, warp tile 64x32), K-chunk 32, 2 stages.
// smem stage: AH(10240) AL BH BL -> 40960 B; 2 stages = 81920 B. Row stride
// 40 bf16 (80 B, odd multiple of 16B -> ldmatrix conflict-free).
// ===========================================================================
#define G_STAGE 40960
#define G_PART  10240
#define G_SMEM  (2 * G_STAGE)

__global__ __launch_bounds__(256, 1) void gemm_mma(
    const float* __restrict__ A, const float* __restrict__ Bm,
    float* __restrict__ C, int Kd, int Nd)
{
    extern __shared__ char smem[];
    const uint32_t sb = smem_u32(smem);
    const int tid = threadIdx.x;
    const int wid = tid >> 5, lane = tid & 31;
    const int wm = wid >> 2, wn = wid & 3;
    const int m0 = blockIdx.y * 128, n0 = blockIdx.x * 128;
    const int nch = Kd / 32;

    const int prow = tid >> 1;          // 0..127
    const int pks  = (tid & 1) * 16;    // 0 / 16
    const float* Ap = A + (size_t)(m0 + prow) * Kd + pks;
    const float* Bp = Bm + (size_t)(n0 + prow) * Kd + pks;

    float4 apf[4], bpf[4];
    float acc[4][4][4];
#pragma unroll
    for (int i = 0; i < 4; i++)
#pragma unroll
        for (int j = 0; j < 4; j++)
#pragma unroll
            for (int e = 0; e < 4; e++) acc[i][j][e] = 0.f;

    // ---- helpers as lambdas ----
    auto load_regs = [&](int c) {
#pragma unroll
        for (int j = 0; j < 4; j++) {
            apf[j] = *(const float4*)(Ap + c * 32 + j * 4);
            bpf[j] = *(const float4*)(Bp + c * 32 + j * 4);
        }
    };
    auto sts_regs = [&](int s) {
        const uint32_t st = sb + s * G_STAGE;
        const uint32_t rowoff = prow * 80 + pks * 2;
#pragma unroll
        for (int j = 0; j < 4; j++) {
            uint32_t addr = st + rowoff + j * 8;
            uint32_t h0 = packbf(apf[j].x, apf[j].y);
            uint32_t h1 = packbf(apf[j].z, apf[j].w);
            uint32_t l0 = packbf(apf[j].x - bfx2_lo(h0), apf[j].y - bfx2_hi(h0));
            uint32_t l1 = packbf(apf[j].z - bfx2_lo(h1), apf[j].w - bfx2_hi(h1));
            STSV2(addr, h0, h1);
            STSV2(addr + G_PART, l0, l1);
            h0 = packbf(bpf[j].x, bpf[j].y);
            h1 = packbf(bpf[j].z, bpf[j].w);
            l0 = packbf(bpf[j].x - bfx2_lo(h0), bpf[j].y - bfx2_hi(h0));
            l1 = packbf(bpf[j].z - bfx2_lo(h1), bpf[j].w - bfx2_hi(h1));
            STSV2(addr + 2 * G_PART, h0, h1);
            STSV2(addr + 3 * G_PART, l0, l1);
        }
    };
    auto compute = [&](int s) {
        const uint32_t st = sb + s * G_STAGE;
        const uint32_t lrow = (lane & 15);
        const uint32_t lcol = (lane >> 4) * 16;
#pragma unroll
        for (int k16 = 0; k16 < 2; k16++) {
            const uint32_t kb2 = k16 * 32;
            uint32_t ah[4][4], al[4][4];
#pragma unroll
            for (int i = 0; i < 4; i++) {
                uint32_t aaddr = st + (wm * 64 + i * 16 + lrow) * 80 + kb2 + lcol;
                LDMX4(ah[i], aaddr);
                LDMX4(al[i], aaddr + G_PART);
            }
            uint32_t bh_[4][2], bl_[4][2];
#pragma unroll
            for (int jj = 0; jj < 2; jj++) {
                uint32_t r[4];
                uint32_t baddr = st + 2 * G_PART + (wn * 32 + jj * 16 + lrow) * 80 + kb2 + lcol;
                LDMX4(r, baddr);
                bh_[2 * jj][0] = r[0]; bh_[2 * jj][1] = r[2];
                bh_[2 * jj + 1][0] = r[1]; bh_[2 * jj + 1][1] = r[3];
                LDMX4(r, baddr + G_PART);
                bl_[2 * jj][0] = r[0]; bl_[2 * jj][1] = r[2];
                bl_[2 * jj + 1][0] = r[1]; bl_[2 * jj + 1][1] = r[3];
            }
#pragma unroll
            for (int i = 0; i < 4; i++)
#pragma unroll
                for (int j = 0; j < 4; j++) {
                    MMA_BF16(acc[i][j], ah[i], bh_[j][0], bh_[j][1]);
                    MMA_BF16(acc[i][j], al[i], bh_[j][0], bh_[j][1]);
                    MMA_BF16(acc[i][j], ah[i], bl_[j][0], bl_[j][1]);
                }
        }
    };

    // ---- main loop: reg-prefetch + smem double buffer ----
    load_regs(0);
    sts_regs(0);
    __syncthreads();
    for (int c = 0; c < nch; c++) {
        if (c + 1 < nch) load_regs(c + 1);
        compute(c & 1);
        __syncthreads();
        if (c + 1 < nch) {
            sts_regs((c + 1) & 1);
            __syncthreads();
        }
    }

    // ---- epilogue ----
    const int r = lane >> 2;
    const int cb = (lane & 3) * 2;
#pragma unroll
    for (int i = 0; i < 4; i++) {
        const int row0 = m0 + wm * 64 + i * 16 + r;
#pragma unroll
        for (int j = 0; j < 4; j++) {
            const int col = n0 + wn * 32 + j * 8 + cb;
            *(float2*)(C + (size_t)row0 * Nd + col) = make_float2(acc[i][j][0], acc[i][j][1]);
            *(float2*)(C + (size_t)(row0 + 8) * Nd + col) = make_float2(acc[i][j][2], acc[i][j][3]);
        }
    }
}

// ---------------------------------------------------------------------------
// prep: per (b,t,h) RMS-norm q,k; RoPE; v-mix. Emits bf16-split Q,K in
// [B,H,T,D] and fp32 V in [B,H,T,D] (transposed+split by vtrans).
// ---------------------------------------------------------------------------
__global__ __launch_bounds__(128) void prep_kernel(
    const float* __restrict__ qkv, const float* __restrict__ ve,
    const float* __restrict__ lam,
    __nv_bfloat16* __restrict__ Qh, __nv_bfloat16* __restrict__ Ql,
    __nv_bfloat16* __restrict__ Kh, __nv_bfloat16* __restrict__ Kl,
    float* __restrict__ V)
{
    const int idx = blockIdx.x;          // (b*T + t)*H + h
    const int h = idx % NH;
    const int bt = idx / NH;
    const int t = bt % SEQ;
    const int b = bt / SEQ;
    const int d = threadIdx.x;

    const float* base = qkv + (size_t)bt * 3 * HDIM;
    float qv = base[h * HD + d];
    float kv = base[HDIM + h * HD + d];
    float vv = base[2 * HDIM + h * HD + d];

    float sq = qv * qv, sk = kv * kv;
#pragma unroll
    for (int o = 16; o; o >>= 1) {
        sq += __shfl_xor_sync(0xffffffffu, sq, o);
        sk += __shfl_xor_sync(0xffffffffu, sk, o);
    }
    __shared__ float wq[4], wk[4];
    if ((d & 31) == 0) { wq[d >> 5] = sq; wk[d >> 5] = sk; }
    __syncthreads();
    float tq = (wq[0] + wq[1]) + (wq[2] + wq[3]);
    float tk = (wk[0] + wk[1]) + (wk[2] + wk[3]);
    const float EPS = 1.1920929e-7f;
    float rq = rsqrtf(tq * (1.0f / 128.0f) + EPS);
    float rk = rsqrtf(tk * (1.0f / 128.0f) + EPS);

    __shared__ float nq[128], nk[128];
    nq[d] = qv * rq;
    nk[d] = kv * rk;
    __syncthreads();

    const int i = d & 63;
    float c, s;
    if (i < 32) {
        float xi = (float)i / 31.0f;
        float f = (float)exp2(-10.0 * (double)xi);
        float th = (float)t * f;
        c = cosf(th);
        s = sinf(th);
    } else {
        c = 1.0f; s = 0.0f;
    }
    float qo, ko;
    if (d < 64) { qo = nq[d] * c + nq[d + 64] * s; ko = nk[d] * c + nk[d + 64] * s; }
    else        { qo = nq[d] * c - nq[d - 64] * s; ko = nk[d] * c - nk[d - 64] * s; }

    float vo = lam[0] * vv + lam[1] * ve[(size_t)bt * HDIM + h * HD + d];

    size_t o = ((size_t)(b * NH + h) * SEQ + t) * HD + d;
    __nv_bfloat16 qhi = __float2bfloat16(qo);
    __nv_bfloat16 khi = __float2bfloat16(ko);
    Qh[o] = qhi; Ql[o] = __float2bfloat16(qo - __bfloat162float(qhi));
    Kh[o] = khi; Kl[o] = __float2bfloat16(ko - __bfloat162float(khi));
    V[o] = vo;
}

// ---------------------------------------------------------------------------
// vtrans: V [BH][T][D] fp32 -> Vh/Vl [BH][D][T] bf16 split (32x32 smem tiles)
// ---------------------------------------------------------------------------
__global__ __launch_bounds__(256) void vtrans_kernel(
    const float* __restrict__ V,
    __nv_bfloat16* __restrict__ Vh, __nv_bfloat16* __restrict__ Vl)
{
    __shared__ float tile[32][33];
    const int bh = blockIdx.z;
    const int t0 = blockIdx.x * 32, d0 = blockIdx.y * 32;
    const int tx = threadIdx.x & 31, ty = threadIdx.x >> 5;   // 32 x 8
    const float* src = V + (size_t)bh * SEQ * HD;
#pragma unroll
    for (int i = 0; i < 4; i++)
        tile[ty + i * 8][tx] = src[(size_t)(t0 + ty + i * 8) * HD + d0 + tx];
    __syncthreads();
    __nv_bfloat16* dh = Vh + (size_t)bh * HD * SEQ;
    __nv_bfloat16* dl = Vl + (size_t)bh * HD * SEQ;
#pragma unroll
    for (int i = 0; i < 4; i++) {
        float v = tile[tx][ty + i * 8];
        __nv_bfloat16 hi = __float2bfloat16(v);
        size_t o = (size_t)(d0 + ty + i * 8) * SEQ + t0 + tx;
        dh[o] = hi;
        dl[o] = __float2bfloat16(v - __bfloat162float(hi));
    }
}

// ===========================================================================
// Flash attention, bf16-split mma. CTA: 128 q-rows, 8 warps x 16 rows.
// Q (hi/lo) resident in smem; K/V (hi/lo) double-buffered via cp.async.
// S = Q@K^T (3 mma terms), fp32 online softmax on fragments, P repacked
// in-register as A-operand for P@V (3 terms). Causal tile skip.
// smem: QH 34816 | QL 34816 | stage{KH 17408|KL|VH 18432|VL} x2 = 212992 B
// ===========================================================================
#define FQ_PART 34816
#define FK_PART 17408
#define FV_PART 18432
#define FSTAGE  (2 * FK_PART + 2 * FV_PART)     // 71680
#define FSTAGE0 (2 * FQ_PART)                   // 69632
#define F_SMEM  (FSTAGE0 + 2 * FSTAGE)          // 212992

__global__ __launch_bounds__(256, 1) void flash_mma(
    const __nv_bfloat16* __restrict__ Qh, const __nv_bfloat16* __restrict__ Ql,
    const __nv_bfloat16* __restrict__ Kh, const __nv_bfloat16* __restrict__ Kl,
    const __nv_bfloat16* __restrict__ Vh, const __nv_bfloat16* __restrict__ Vl,
    float* __restrict__ Y)
{
    extern __shared__ char smem[];
    const uint32_t sbase = smem_u32(smem);
    const int tid = threadIdx.x;
    const int wid = tid >> 5, lane = tid & 31;
    const int qt = gridDim.x - 1 - blockIdx.x;      // big tiles first
    const int bh = blockIdx.y;
    const int b = bh >> 3, h = bh & 7;

    const size_t TD = (size_t)SEQ * HD;
    const __nv_bfloat16* qh_b = Qh + bh * TD;
    const __nv_bfloat16* ql_b = Ql + bh * TD;
    const __nv_bfloat16* kh_b = Kh + bh * TD;
    const __nv_bfloat16* kl_b = Kl + bh * TD;
    const __nv_bfloat16* vh_b = Vh + bh * TD;
    const __nv_bfloat16* vl_b = Vl + bh * TD;

    // ---- async load of the Q tile (both parts) ----
#pragma unroll
    for (int i = 0; i < 16; i++) {
        int c = i * 256 + tid;
        int part = c >> 11;              // 2048 16B-chunks per part
        int c2 = c & 2047;
        int row = c2 >> 4, col = c2 & 15;
        uint32_t dst = sbase + part * FQ_PART + row * 272 + col * 16;
        const __nv_bfloat16* src = (part ? ql_b : qh_b) + (size_t)(qt * 128 + row) * 128 + col * 8;
        CP_ASYNC16(dst, src);
    }
    auto load_kv = [&](int kt, int s) {
        uint32_t kb = sbase + FSTAGE0 + s * FSTAGE;
#pragma unroll
        for (int i = 0; i < 4; i++) {
            int c = i * 256 + tid;
            int row = c >> 4, col = c & 15;
            uint32_t off = row * 272 + col * 16;
            size_t gi = (size_t)(kt * 64 + row) * 128 + col * 8;
            CP_ASYNC16(kb + off, kh_b + gi);
            CP_ASYNC16(kb + FK_PART + off, kl_b + gi);
        }
#pragma unroll
        for (int i = 0; i < 4; i++) {
            int c = i * 256 + tid;
            int row = c >> 3, col = c & 7;
            uint32_t off = row * 144 + col * 16;
            size_t gi = (size_t)row * SEQ + kt * 64 + col * 8;
            CP_ASYNC16(kb + 2 * FK_PART + off, vh_b + gi);
            CP_ASYNC16(kb + 2 * FK_PART + FV_PART + off, vl_b + gi);
        }
    };
    load_kv(0, 0);
    CP_COMMIT();

    float acc[16][4];
#pragma unroll
    for (int i = 0; i < 16; i++)
#pragma unroll
        for (int e = 0; e < 4; e++) acc[i][e] = 0.f;
    float m_i[2] = {-1e30f, -1e30f};
    float l_i[2] = {0.f, 0.f};

    const uint32_t lrow = lane & 15;
    const uint32_t lcol = (lane >> 4) * 16;
    const int nkt = 2 * qt + 2;
    const float SC = 0.08838834764831845f;   // 1/sqrt(128)

    for (int kt = 0; kt < nkt; kt++) {
        if (kt + 1 < nkt) {
            load_kv(kt + 1, (kt + 1) & 1);
            CP_COMMIT();
            CP_WAIT1();
        } else {
            CP_WAIT0();
        }
        __syncthreads();
        const uint32_t kb = sbase + FSTAGE0 + (kt & 1) * FSTAGE;

        // ---------- S = Q @ K^T ----------
        float s[8][4];
#pragma unroll
        for (int j = 0; j < 8; j++)
#pragma unroll
            for (int e = 0; e < 4; e++) s[j][e] = 0.f;

        const uint32_t qrow = sbase + (wid * 16 + lrow) * 272 + lcol;
#pragma unroll
        for (int k16 = 0; k16 < 8; k16++) {
            uint32_t qa = qrow + k16 * 32;
            uint32_t ah[4], al[4];
            LDMX4(ah, qa);
            LDMX4(al, qa + FQ_PART);
#pragma unroll
            for (int jj = 0; jj < 4; jj++) {
                uint32_t ka = kb + (jj * 16 + lrow) * 272 + lcol + k16 * 32;
                uint32_t r[4];
                LDMX4(r, ka);
                MMA_BF16(s[2 * jj], ah, r[0], r[2]);
                MMA_BF16(s[2 * jj + 1], ah, r[1], r[3]);
                MMA_BF16(s[2 * jj], al, r[0], r[2]);
                MMA_BF16(s[2 * jj + 1], al, r[1], r[3]);
                LDMX4(r, ka + FK_PART);
                MMA_BF16(s[2 * jj], ah, r[0], r[2]);
                MMA_BF16(s[2 * jj + 1], ah, r[1], r[3]);
            }
        }

        // ---------- scale + causal mask + online softmax ----------
        const bool need_mask = (kt >= 2 * qt);
#pragma unroll
        for (int hh = 0; hh < 2; hh++) {
            const int rowg = qt * 128 + wid * 16 + (lane >> 2) + hh * 8;
            float mt = -1e30f;
#pragma unroll
            for (int j = 0; j < 8; j++) {
#pragma unroll
                for (int e = 0; e < 2; e++) {
                    float v = s[j][2 * hh + e] * SC;
                    if (need_mask) {
                        int colg = kt * 64 + j * 8 + (lane & 3) * 2 + e;
                        if (colg > rowg) v = -1e30f;
                    }
                    s[j][2 * hh + e] = v;
                    mt = fmaxf(mt, v);
                }
            }
            mt = fmaxf(mt, __shfl_xor_sync(0xffffffffu, mt, 1));
            mt = fmaxf(mt, __shfl_xor_sync(0xffffffffu, mt, 2));
            float mn = fmaxf(m_i[hh], mt);
            float corr = __expf(m_i[hh] - mn);
            m_i[hh] = mn;
            float rs = 0.f;
#pragma unroll
            for (int j = 0; j < 8; j++) {
#pragma unroll
                for (int e = 0; e < 2; e++) {
                    float p = __expf(s[j][2 * hh + e] - mn);
                    s[j][2 * hh + e] = p;
                    rs += p;
                }
            }
            rs += __shfl_xor_sync(0xffffffffu, rs, 1);
            rs += __shfl_xor_sync(0xffffffffu, rs, 2);
            l_i[hh] = l_i[hh] * corr + rs;
#pragma unroll
            for (int ot = 0; ot < 16; ot++) {
                acc[ot][2 * hh] *= corr;
                acc[ot][2 * hh + 1] *= corr;
            }
        }

        // ---------- acc += P @ V ----------
        const uint32_t vb = kb + 2 * FK_PART;
#pragma unroll
        for (int kk = 0; kk < 4; kk++) {
            const int j0 = 2 * kk, j1 = 2 * kk + 1;
            uint32_t ahp[4], alp[4];
            ahp[0] = packbf(s[j0][0], s[j0][1]);
            ahp[1] = packbf(s[j0][2], s[j0][3]);
            ahp[2] = packbf(s[j1][0], s[j1][1]);
            ahp[3] = packbf(s[j1][2], s[j1][3]);
            alp[0] = packbf(s[j0][0] - bfx2_lo(ahp[0]), s[j0][1] - bfx2_hi(ahp[0]));
            alp[1] = packbf(s[j0][2] - bfx2_lo(ahp[1]), s[j0][3] - bfx2_hi(ahp[1]));
            alp[2] = packbf(s[j1][0] - bfx2_lo(ahp[2]), s[j1][1] - bfx2_hi(ahp[2]));
            alp[3] = packbf(s[j1][2] - bfx2_lo(ahp[3]), s[j1][3] - bfx2_hi(ahp[3]));
#pragma unroll
            for (int jj = 0; jj < 8; jj++) {
                uint32_t va = vb + (jj * 16 + lrow) * 144 + kk * 32 + lcol;
                uint32_t r[4];
                LDMX4(r, va);
                MMA_BF16(acc[2 * jj], ahp, r[0], r[2]);
                MMA_BF16(acc[2 * jj + 1], ahp, r[1], r[3]);
                MMA_BF16(acc[2 * jj], alp, r[0], r[2]);
                MMA_BF16(acc[2 * jj + 1], alp, r[1], r[3]);
                LDMX4(r, va + FV_PART);
                MMA_BF16(acc[2 * jj], ahp, r[0], r[2]);
                MMA_BF16(acc[2 * jj + 1], ahp, r[1], r[3]);
            }
        }
        __syncthreads();
    }

    // ---------- epilogue ----------
    const float inv0 = 1.f / l_i[0];
    const float inv1 = 1.f / l_i[1];
    const int r0 = qt * 128 + wid * 16 + (lane >> 2);
    const int cb = (lane & 3) * 2;
#pragma unroll
    for (int ot = 0; ot < 16; ot++) {
        const int d = ot * 8 + cb;
        float* y0 = Y + ((size_t)b * SEQ + r0) * HDIM + h * HD + d;
        float* y1 = y0 + (size_t)8 * HDIM;
        *(float2*)y0 = make_float2(acc[ot][0] * inv0, acc[ot][1] * inv0);
        *(float2*)y1 = make_float2(acc[ot][2] * inv1, acc[ot][3] * inv1);
    }
}

// ---------------------------------------------------------------------------
extern "C" void kernel_launch(void* const* d_in, const int* in_sizes, int n_in,
                              void* d_out, int out_size)
{
    const float* x        = (const float*)d_in[0];
    const float* ve       = (const float*)d_in[1];
    const float* qkv_w    = (const float*)d_in[2];   // [3*HDIM, DIM]
    const float* lambdas  = (const float*)d_in[3];
    const float* c_proj_w = (const float*)d_in[4];   // [DIM, HDIM]
    float* out = (float*)d_out;

    float *qkv, *V, *Y;
    __nv_bfloat16 *Qh, *Ql, *Kh, *Kl, *Vh, *Vl;
    cudaGetSymbolAddress((void**)&qkv, g_qkv);
    cudaGetSymbolAddress((void**)&V, g_v);
    cudaGetSymbolAddress((void**)&Y, g_y);
    cudaGetSymbolAddress((void**)&Qh, g_qh);
    cudaGetSymbolAddress((void**)&Ql, g_ql);
    cudaGetSymbolAddress((void**)&Kh, g_kh);
    cudaGetSymbolAddress((void**)&Kl, g_kl);
    cudaGetSymbolAddress((void**)&Vh, g_vh);
    cudaGetSymbolAddress((void**)&Vl, g_vl);

    cudaFuncSetAttribute(gemm_mma, cudaFuncAttributeMaxDynamicSharedMemorySize, G_SMEM);
    cudaFuncSetAttribute(flash_mma, cudaFuncAttributeMaxDynamicSharedMemorySize, F_SMEM);

    // 1) qkv = x @ qkv_w^T : [8192,1024] x [3072,1024]^T
    gemm_mma<<<dim3(3 * HDIM / 128, BATCH * SEQ / 128), 256, G_SMEM>>>(
        x, qkv_w, qkv, DMODEL, 3 * HDIM);

    // 2) rms-norm + rope + v-mix -> bf16 splits
    prep_kernel<<<BATCH * SEQ * NH, 128>>>(qkv, ve, lambdas, Qh, Ql, Kh, Kl, V);

    // 2b) V transpose + split -> [B,H,D,T]
    vtrans_kernel<<<dim3(SEQ / 32, HD / 32, BATCH * NH), 256>>>(V, Vh, Vl);

    // 3) causal flash attention (tensor cores) -> Y [B,T,HDIM]
    flash_mma<<<dim3(SEQ / 128, BATCH * NH), 256, F_SMEM>>>(
        Qh, Ql, Kh, Kl, Vh, Vl, Y);

    // 4) out = Y @ c_proj_w^T : [8192,1024] x [1024,1024]^T
    gemm_mma<<<dim3(DMODEL / 128, BATCH * SEQ / 128), 256, G_SMEM>>>(
        Y, c_proj_w, out, HDIM, DMODEL);
}